// round 3
// baseline (speedup 1.0000x reference)
#include <cuda_runtime.h>
#include <cuda_fp16.h>
#include <cstdint>

// ======================= problem constants =======================
// B=128, T=1024, M=512 (GEMM N), P=256, K=512, rows = B*T = 131072
static constexpr int NB      = 128;
static constexpr int TLEN    = 1024;
static constexpr int MDIM    = 512;    // N of GEMM
static constexpr int KDIM    = 512;    // inner dim
static constexpr int MTILE   = 128;    // rows per CTA
static constexpr int NCHUNK  = 32;     // N per B chunk (double-buffered)
static constexpr int NCHUNKS = MDIM / NCHUNK;   // 16

// padded row strides (fp16 elems): +16B/row rotates bank groups -> conflict-free ldmatrix
static constexpr int APAD = 520;
static constexpr int BPAD = 520;

static constexpr int SMEM_A_BYTES    = MTILE * APAD * 2;     // 133120
static constexpr int SMEM_BBUF_BYTES = NCHUNK * BPAD * 2;    // 33280
static constexpr int DYN_SMEM = SMEM_A_BYTES + 2 * SMEM_BBUF_BYTES;  // 199680

// ======================= scratch (device globals; no allocs) =======================
__device__ float g_Qt[KDIM * NB];                    // Q transposed [c][b]
__device__ float g_wq[NB * MDIM];                    // wq[b][n]
__device__ __align__(16) __half g_U16[MDIM * KDIM];  // U_d as fp16, [n][k]

// ======================= helpers =======================
__device__ __forceinline__ uint32_t smem_u32(const void* p) {
    return (uint32_t)__cvta_generic_to_shared(p);
}

__device__ __forceinline__ uint32_t pack_h2(float a, float b) {
    __half2 h = __floats2half2_rn(a, b);
    return *reinterpret_cast<uint32_t*>(&h);
}

__device__ __forceinline__ void ldsm_x4(uint32_t addr, uint32_t& r0, uint32_t& r1,
                                        uint32_t& r2, uint32_t& r3) {
    asm volatile("ldmatrix.sync.aligned.m8n8.x4.shared.b16 {%0,%1,%2,%3}, [%4];"
                 : "=r"(r0), "=r"(r1), "=r"(r2), "=r"(r3) : "r"(addr));
}

__device__ __forceinline__ void mma16816(float& c0, float& c1, float& c2, float& c3,
                                         uint32_t a0, uint32_t a1, uint32_t a2, uint32_t a3,
                                         uint32_t b0, uint32_t b1) {
    asm volatile(
        "mma.sync.aligned.m16n8k16.row.col.f32.f16.f16.f32 "
        "{%0,%1,%2,%3}, {%4,%5,%6,%7}, {%8,%9}, {%0,%1,%2,%3};"
        : "+f"(c0), "+f"(c1), "+f"(c2), "+f"(c3)
        : "r"(a0), "r"(a1), "r"(a2), "r"(a3), "r"(b0), "r"(b1));
}

__device__ __forceinline__ void cp_async16(uint32_t dst, const void* src) {
    asm volatile("cp.async.cg.shared.global [%0], [%1], 16;" :: "r"(dst), "l"(src));
}
__device__ __forceinline__ void cp_commit() {
    asm volatile("cp.async.commit_group;" ::: "memory");
}
__device__ __forceinline__ void cp_wait1() {
    asm volatile("cp.async.wait_group 1;" ::: "memory");
}
__device__ __forceinline__ void cp_wait0() {
    asm volatile("cp.async.wait_group 0;" ::: "memory");
}

// tanh(x) = 1 - 2/(e^{2x}+1): 2 MUFU + few ALU, rel err ~1e-6 (vs tanh.approx ~6e-4)
__device__ __forceinline__ float fast_tanh(float x) {
    float e = __expf(x + x);
    return 1.0f - __fdividef(2.0f, e + 1.0f);
}

// ======================= kernel 1: pack Qt + U -> fp16 =======================
__global__ void __launch_bounds__(256, 1) pack_kernel(const float* __restrict__ dt,
                                                      const float* __restrict__ st,
                                                      const float* __restrict__ Ud) {
    int tid = blockIdx.x * blockDim.x + threadIdx.x;
    int stride = gridDim.x * blockDim.x;
    for (int i = tid; i < KDIM * NB; i += stride) {
        int c = i >> 7, b = i & (NB - 1);
        float v = (c < 256) ? dt[b * 256 + c] : st[b * 256 + (c - 256)];
        g_Qt[c * NB + b] = v;
    }
    for (int i = tid; i < MDIM * KDIM; i += stride)
        g_U16[i] = __float2half_rn(Ud[i]);
}

// ======================= kernel 2: wq[b][n] = sum_c q[b][c]*W_d[n][c] =======================
__global__ void __launch_bounds__(128, 1) wq_kernel(const float* __restrict__ Wd) {
    __shared__ float Ws[8 * KDIM];
    int nbase = blockIdx.x * 8;
    for (int i = threadIdx.x; i < 8 * KDIM; i += 128)
        Ws[i] = Wd[nbase * KDIM + i];
    __syncthreads();
    int b = threadIdx.x;
    float acc[8];
#pragma unroll
    for (int j = 0; j < 8; j++) acc[j] = 0.0f;
    for (int c = 0; c < KDIM; c++) {
        float qv = g_Qt[c * NB + b];
#pragma unroll
        for (int j = 0; j < 8; j++) acc[j] = fmaf(qv, Ws[j * KDIM + c], acc[j]);
    }
#pragma unroll
    for (int j = 0; j < 8; j++) g_wq[b * MDIM + nbase + j] = acc[j];
}

// ======================= kernel 3: fused GEMM(HMMA) + tanh + v-dot =======================
// grid = 1024 CTAs, 512 threads (16 warps).
// warp w: rowgrp = w>>1 (16 rows), ngrp = w&1 (16 n within a 32-n chunk)
__global__ void __launch_bounds__(512, 1) attn_gemm_kernel(const float* __restrict__ H,
                                                           const float* __restrict__ vd,
                                                           float* __restrict__ out) {
    extern __shared__ __align__(16) char dsm[];
    __half* smemA = reinterpret_cast<__half*>(dsm);
    char*   smemB = dsm + SMEM_A_BYTES;

    __shared__ float wq_s[MDIM];
    __shared__ float v_s[MDIM];
    __shared__ float score2[2][MTILE];

    const int tid  = threadIdx.x;
    const int wid  = tid >> 5;
    const int lane = tid & 31;
    const int blk  = blockIdx.x;
    const int batch = blk >> 3;
    const size_t r0 = (size_t)blk * MTILE;

    for (int i = tid; i < MDIM; i += 512) {
        wq_s[i] = g_wq[batch * MDIM + i];
        v_s[i]  = vd[i];
    }

    // ---- B chunk issue helper (inline below): chunk c -> buffer b ----
    const uint32_t sb_u32_0 = smem_u32(smemB);
    const uint32_t sb_u32_1 = sb_u32_0 + SMEM_BBUF_BYTES;
    const int brow = tid >> 4;           // reuse mapping: idx = tid + it*512
    // issue chunk 0 and 1 first: cp.async (L2 hits) overlap with A convert below
    {
#pragma unroll
        for (int it = 0; it < 4; it++) {
            int idx = tid + it * 512;
            int row = idx >> 6, c16 = idx & 63;
            cp_async16(sb_u32_0 + (uint32_t)(row * (BPAD * 2) + c16 * 16),
                       (const char*)g_U16 + row * 1024 + c16 * 16);
        }
        cp_commit();
#pragma unroll
        for (int it = 0; it < 4; it++) {
            int idx = tid + it * 512;
            int row = idx >> 6, c16 = idx & 63;
            cp_async16(sb_u32_1 + (uint32_t)(row * (BPAD * 2) + c16 * 16),
                       (const char*)g_U16 + (size_t)NCHUNK * KDIM * 2 + row * 1024 + c16 * 16);
        }
        cp_commit();
    }
    (void)brow;

    // ---- load A: 128 rows x 512 K, fp32 -> fp16, padded rows ----
    {
#pragma unroll
        for (int it = 0; it < 16; it++) {
            int idx = tid + it * 512;
            int row = idx >> 6;
            int c8  = idx & 63;
            const float4* src = reinterpret_cast<const float4*>(
                H + (r0 + (size_t)row) * KDIM + c8 * 8);
            float4 f0 = src[0], f1 = src[1];
            uint4 u;
            u.x = pack_h2(f0.x, f0.y); u.y = pack_h2(f0.z, f0.w);
            u.z = pack_h2(f1.x, f1.y); u.w = pack_h2(f1.z, f1.w);
            *reinterpret_cast<uint4*>(smemA + row * APAD + c8 * 8) = u;
        }
    }
    cp_wait1();          // chunk 0 landed
    __syncthreads();     // A + B0 visible to all

    // ---- per-lane ldmatrix addressing ----
    const int sub = lane >> 3;
    const int l8  = lane & 7;
    const int rowgrp = wid >> 1;
    const int ngrp   = wid & 1;
    const int rbase  = rowgrp * 16;

    const uint32_t aAddrBase = smem_u32(smemA) +
        (uint32_t)(((rbase + (sub & 1) * 8 + l8) * APAD + (sub >> 1) * 8) * 2);
    // B tiles within buffer: t0 n0-7/k0-7, t1 n0-7/k8-15, t2 n8-15/k0-7, t3 n8-15/k8-15
    const uint32_t bOff = (uint32_t)(((ngrp * 16 + (sub >> 1) * 8 + l8) * BPAD + (sub & 1) * 8) * 2);
    const uint32_t bAddrBuf[2] = { sb_u32_0 + bOff, sb_u32_1 + bOff };

    const int qn = (lane & 3) * 2;
    float s0 = 0.0f, s1 = 0.0f;   // running row-scores (deferred reduction)

    for (int c = 0; c < NCHUNKS; c++) {
        const uint32_t bA = bAddrBuf[c & 1];

        float acc[2][4];
#pragma unroll
        for (int t = 0; t < 2; t++)
#pragma unroll
            for (int j = 0; j < 4; j++) acc[t][j] = 0.0f;

#pragma unroll 4
        for (int ks = 0; ks < 32; ks++) {
            uint32_t a0, a1, a2, a3, p0, p1, p2, p3;
            ldsm_x4(aAddrBase + ks * 32, a0, a1, a2, a3);
            ldsm_x4(bA + ks * 32, p0, p1, p2, p3);
            mma16816(acc[0][0], acc[0][1], acc[0][2], acc[0][3], a0, a1, a2, a3, p0, p1);
            mma16816(acc[1][0], acc[1][1], acc[1][2], acc[1][3], a0, a1, a2, a3, p2, p3);
        }

        // ---- fused epilogue: tanh + v-dot, accumulate into registers ----
        const int nb = c * NCHUNK + ngrp * 16;
#pragma unroll
        for (int t = 0; t < 2; t++) {
            int n = nb + t * 8 + qn;
            float w0 = wq_s[n], w1 = wq_s[n + 1];
            float v0 = v_s[n],  v1 = v_s[n + 1];
            s0 = fmaf(v0, fast_tanh(w0 + acc[t][0]), s0);
            s0 = fmaf(v1, fast_tanh(w1 + acc[t][1]), s0);
            s1 = fmaf(v0, fast_tanh(w0 + acc[t][2]), s1);
            s1 = fmaf(v1, fast_tanh(w1 + acc[t][3]), s1);
        }

        __syncthreads();   // all warps done reading buf[c&1]
        if (c + 2 < NCHUNKS) {
            const char* src = (const char*)g_U16 + (size_t)(c + 2) * NCHUNK * KDIM * 2;
            uint32_t dst = bAddrBuf[0] - bOff + (uint32_t)((c & 1) * SMEM_BBUF_BYTES);
#pragma unroll
            for (int it = 0; it < 4; it++) {
                int idx = tid + it * 512;
                int row = idx >> 6, c16 = idx & 63;
                cp_async16(dst + (uint32_t)(row * (BPAD * 2) + c16 * 16),
                           src + row * 1024 + c16 * 16);
            }
            cp_commit();
        }
        if (c + 1 < NCHUNKS) {
            if (c + 2 < NCHUNKS) cp_wait1(); else cp_wait0();
            __syncthreads();   // chunk c+1 visible
        }
    }

    // ---- final reduction: quad shuffle + 2-warp array ----
    s0 += __shfl_xor_sync(0xffffffffu, s0, 1);
    s0 += __shfl_xor_sync(0xffffffffu, s0, 2);
    s1 += __shfl_xor_sync(0xffffffffu, s1, 1);
    s1 += __shfl_xor_sync(0xffffffffu, s1, 2);
    if ((lane & 3) == 0) {
        score2[ngrp][rbase + (lane >> 2)]     = s0;
        score2[ngrp][rbase + 8 + (lane >> 2)] = s1;
    }
    __syncthreads();
    if (tid < MTILE) out[r0 + tid] = score2[0][tid] + score2[1][tid];
}

// ======================= kernel 4: softmax over T, in-place =======================
__global__ void __launch_bounds__(256, 1) softmax_kernel(float* __restrict__ out) {
    __shared__ float red[256];
    float* p = out + (size_t)blockIdx.x * TLEN;
    int tid = threadIdx.x;
    float v[4];
    float m = -1e30f;
#pragma unroll
    for (int j = 0; j < 4; j++) { v[j] = p[tid + j * 256]; m = fmaxf(m, v[j]); }
    red[tid] = m; __syncthreads();
    for (int s = 128; s > 0; s >>= 1) {
        if (tid < s) red[tid] = fmaxf(red[tid], red[tid + s]);
        __syncthreads();
    }
    float mx = red[0];
    __syncthreads();
    float sum = 0.0f;
#pragma unroll
    for (int j = 0; j < 4; j++) { v[j] = __expf(v[j] - mx); sum += v[j]; }
    red[tid] = sum; __syncthreads();
    for (int s = 128; s > 0; s >>= 1) {
        if (tid < s) red[tid] += red[tid + s];
        __syncthreads();
    }
    float inv = 1.0f / red[0];
#pragma unroll
    for (int j = 0; j < 4; j++) p[tid + j * 256] = v[j] * inv;
}

// ======================= launch =======================
extern "C" void kernel_launch(void* const* d_in, const int* in_sizes, int n_in,
                              void* d_out, int out_size) {
    const float *dt = nullptr, *st = nullptr, *H = nullptr;
    const float *W = nullptr, *U = nullptr, *v = nullptr;
    int c32768 = 0, c262144 = 0;
    for (int i = 0; i < n_in; i++) {
        int s = in_sizes[i];
        if (s == 32768)          { if (c32768++ == 0) dt = (const float*)d_in[i]; else st = (const float*)d_in[i]; }
        else if (s == 67108864)  { H = (const float*)d_in[i]; }
        else if (s == 262144)    { if (c262144++ == 0) W = (const float*)d_in[i]; else U = (const float*)d_in[i]; }
        else if (s == 512)       { v = (const float*)d_in[i]; }
    }
    float* out = (float*)d_out;

    cudaFuncSetAttribute(attn_gemm_kernel, cudaFuncAttributeMaxDynamicSharedMemorySize, DYN_SMEM);

    pack_kernel<<<256, 256>>>(dt, st, U);
    wq_kernel<<<64, 128>>>(W);
    attn_gemm_kernel<<<1024, 512, DYN_SMEM>>>(H, v, out);
    softmax_kernel<<<128, 256>>>(out);
}

// round 4
// speedup vs baseline: 1.3314x; 1.3314x over previous
#include <cuda_runtime.h>
#include <cuda_fp16.h>
#include <cstdint>

// ======================= problem constants =======================
// B=128, T=1024, M=512 (GEMM N), P=256, K=512, rows = B*T = 131072
static constexpr int NB      = 128;
static constexpr int TLEN    = 1024;
static constexpr int MDIM    = 512;    // N of GEMM
static constexpr int KDIM    = 512;    // inner dim
static constexpr int MTILE   = 128;    // rows per CTA
static constexpr int NCHUNK  = 256;    // N per chunk (acc-resident)
static constexpr int NCHUNKS = MDIM / NCHUNK;    // 2
static constexpr int KSEG    = 64;     // K per B buffer
static constexpr int KSEGS   = KDIM / KSEG;      // 8
static constexpr int NITER   = NCHUNKS * KSEGS;  // 16

// padded strides (halves): rotate bank groups -> conflict-free ldmatrix
static constexpr int APAD  = 520;      // 1040 B/row
static constexpr int BPAD  = 72;       // 144 B/row (64k + 8 pad)

static constexpr int SMEM_A_BYTES    = MTILE * APAD * 2;        // 133120
static constexpr int SMEM_BBUF_BYTES = NCHUNK * BPAD * 2;       // 36864
static constexpr int DYN_SMEM = SMEM_A_BYTES + 2 * SMEM_BBUF_BYTES;  // 206848

// ======================= scratch (device globals; no allocs) =======================
__device__ float g_Qt[KDIM * NB];                    // Q transposed [c][b]
__device__ float g_wq[NB * MDIM];                    // wq[b][n]
__device__ __align__(16) __half g_U16[MDIM * KDIM];  // U_d as fp16, [n][k]

// ======================= helpers =======================
__device__ __forceinline__ uint32_t smem_u32(const void* p) {
    return (uint32_t)__cvta_generic_to_shared(p);
}
__device__ __forceinline__ uint32_t pack_h2(float a, float b) {
    __half2 h = __floats2half2_rn(a, b);
    return *reinterpret_cast<uint32_t*>(&h);
}
__device__ __forceinline__ void ldsm_x4(uint32_t addr, uint32_t& r0, uint32_t& r1,
                                        uint32_t& r2, uint32_t& r3) {
    asm volatile("ldmatrix.sync.aligned.m8n8.x4.shared.b16 {%0,%1,%2,%3}, [%4];"
                 : "=r"(r0), "=r"(r1), "=r"(r2), "=r"(r3) : "r"(addr));
}
__device__ __forceinline__ void mma16816(float* c,
                                         const uint32_t* a,
                                         uint32_t b0, uint32_t b1) {
    asm volatile(
        "mma.sync.aligned.m16n8k16.row.col.f32.f16.f16.f32 "
        "{%0,%1,%2,%3}, {%4,%5,%6,%7}, {%8,%9}, {%0,%1,%2,%3};"
        : "+f"(c[0]), "+f"(c[1]), "+f"(c[2]), "+f"(c[3])
        : "r"(a[0]), "r"(a[1]), "r"(a[2]), "r"(a[3]), "r"(b0), "r"(b1));
}
__device__ __forceinline__ void cp_async16(uint32_t dst, const void* src) {
    asm volatile("cp.async.cg.shared.global [%0], [%1], 16;" :: "r"(dst), "l"(src));
}
__device__ __forceinline__ void cp_commit() {
    asm volatile("cp.async.commit_group;" ::: "memory");
}
__device__ __forceinline__ void cp_wait1() {
    asm volatile("cp.async.wait_group 1;" ::: "memory");
}
__device__ __forceinline__ void cp_wait0() {
    asm volatile("cp.async.wait_group 0;" ::: "memory");
}
// tanh(x) = 1 - 2/(e^{2x}+1): 2 MUFU + few ALU, rel err ~1e-6
__device__ __forceinline__ float fast_tanh(float x) {
    float e = __expf(x + x);
    return 1.0f - __fdividef(2.0f, e + 1.0f);
}

// ======================= kernel 1: pack Qt + U -> fp16 =======================
__global__ void __launch_bounds__(256, 1) pack_kernel(const float* __restrict__ dt,
                                                      const float* __restrict__ st,
                                                      const float* __restrict__ Ud) {
    int tid = blockIdx.x * blockDim.x + threadIdx.x;
    int stride = gridDim.x * blockDim.x;
    for (int i = tid; i < KDIM * NB; i += stride) {
        int c = i >> 7, b = i & (NB - 1);
        float v = (c < 256) ? dt[b * 256 + c] : st[b * 256 + (c - 256)];
        g_Qt[c * NB + b] = v;
    }
    for (int i = tid; i < MDIM * KDIM; i += stride)
        g_U16[i] = __float2half_rn(Ud[i]);
}

// ======================= kernel 2: wq[b][n] = sum_c q[b][c]*W_d[n][c] =======================
__global__ void __launch_bounds__(128, 1) wq_kernel(const float* __restrict__ Wd) {
    __shared__ float Ws[8 * KDIM];
    int nbase = blockIdx.x * 8;
    for (int i = threadIdx.x; i < 8 * KDIM; i += 128)
        Ws[i] = Wd[nbase * KDIM + i];
    __syncthreads();
    int b = threadIdx.x;
    float acc[8];
#pragma unroll
    for (int j = 0; j < 8; j++) acc[j] = 0.0f;
    for (int c = 0; c < KDIM; c++) {
        float qv = g_Qt[c * NB + b];
#pragma unroll
        for (int j = 0; j < 8; j++) acc[j] = fmaf(qv, Ws[j * KDIM + c], acc[j]);
    }
#pragma unroll
    for (int j = 0; j < 8; j++) g_wq[b * MDIM + nbase + j] = acc[j];
}

// ======================= kernel 3: fused GEMM(HMMA) + tanh + v-dot =======================
// grid = 1024 CTAs, 512 threads (16 warps).
// warp w: rowgrp = w>>2 (32 rows each), ngrp = w&3 (64 n within a 256-n chunk)
__global__ void __launch_bounds__(512, 1) attn_gemm_kernel(const float* __restrict__ H,
                                                           const float* __restrict__ vd,
                                                           float* __restrict__ out) {
    extern __shared__ __align__(16) char dsm[];
    __half* smemA = reinterpret_cast<__half*>(dsm);
    char*   smemB = dsm + SMEM_A_BYTES;

    __shared__ float wq_s[MDIM];
    __shared__ float v_s[MDIM];
    __shared__ float score4[4][MTILE];

    const int tid  = threadIdx.x;
    const int wid  = tid >> 5;
    const int lane = tid & 31;
    const int blk  = blockIdx.x;
    const int batch = blk >> 3;
    const size_t r0 = (size_t)blk * MTILE;

    for (int i = tid; i < MDIM; i += 512) {
        wq_s[i] = g_wq[batch * MDIM + i];
        v_s[i]  = vd[i];
    }

    const uint32_t bbuf0 = smem_u32(smemB);

    // ---- issue B iter 0 (chunk 0, kseg 0) ----
    {
#pragma unroll
        for (int it = 0; it < 4; it++) {
            int idx = tid + it * 512;          // 2048 x 16B
            int row = idx >> 3, c16 = idx & 7;
            cp_async16(bbuf0 + (uint32_t)(row * (BPAD * 2) + c16 * 16),
                       (const char*)g_U16 + row * 1024 + c16 * 16);
        }
        cp_commit();
    }

    // ---- load A: 128 rows x 512 K, fp32 -> fp16, padded rows ----
    {
#pragma unroll
        for (int it = 0; it < 16; it++) {
            int idx = tid + it * 512;
            int row = idx >> 6;
            int c8  = idx & 63;
            const float4* src = reinterpret_cast<const float4*>(
                H + (r0 + (size_t)row) * KDIM + c8 * 8);
            float4 f0 = src[0], f1 = src[1];
            uint4 u;
            u.x = pack_h2(f0.x, f0.y); u.y = pack_h2(f0.z, f0.w);
            u.z = pack_h2(f1.x, f1.y); u.w = pack_h2(f1.z, f1.w);
            *reinterpret_cast<uint4*>(smemA + row * APAD + c8 * 8) = u;
        }
    }

    // ---- per-lane ldmatrix addressing ----
    const int sub = lane >> 3;      // 8x8 tile index within x4
    const int l8  = lane & 7;
    const int rowgrp = wid >> 2;    // 4 rowgrps x 32 rows
    const int ngrp   = wid & 3;     // 4 ngrps x 64 n
    const int rbase  = rowgrp * 32;

    // A x4 tiles: t0 r0-7/k0-7, t1 r8-15/k0-7, t2 r0-7/k8-15, t3 r8-15/k8-15
    const uint32_t aAddr0 = smem_u32(smemA) +
        (uint32_t)(((rbase + (sub & 1) * 8 + l8) * APAD + (sub >> 1) * 8) * 2);
    const uint32_t aAddr1 = aAddr0 + (uint32_t)(16 * APAD * 2);
    // B x4 tiles: t0 n0-7/k0-7, t1 n0-7/k8-15, t2 n8-15/k0-7, t3 n8-15/k8-15
    const uint32_t bOff = (uint32_t)((ngrp * 64 + (sub >> 1) * 8 + l8) * (BPAD * 2) + (sub & 1) * 16);

    const int qn = (lane & 3) * 2;
    float s[4] = {0.0f, 0.0f, 0.0f, 0.0f};   // running row-scores
    float acc[2][8][4];

    for (int i = 0; i < NITER; i++) {
        const int kseg  = i & 7;
        const int chunk = i >> 3;
        if (kseg == 0) {
#pragma unroll
            for (int mt = 0; mt < 2; mt++)
#pragma unroll
                for (int j = 0; j < 8; j++)
#pragma unroll
                    for (int q = 0; q < 4; q++) acc[mt][j][q] = 0.0f;
        }

        __syncthreads();   // prior compute done reading buf[(i+1)&1] (reused below)
        if (i + 1 < NITER) {
            const int j = i + 1;
            const int nb_g = (j >> 3) * NCHUNK;      // chunk base n
            const int ks_g = (j & 7) * (KSEG * 2);   // byte offset in k (fp16)
            const uint32_t dst = bbuf0 + (uint32_t)((j & 1) * SMEM_BBUF_BYTES);
#pragma unroll
            for (int it = 0; it < 4; it++) {
                int idx = tid + it * 512;
                int row = idx >> 3, c16 = idx & 7;
                cp_async16(dst + (uint32_t)(row * (BPAD * 2) + c16 * 16),
                           (const char*)g_U16 + (size_t)(nb_g + row) * 1024 + ks_g + c16 * 16);
            }
            cp_commit();
            cp_wait1();
        } else {
            cp_wait0();
        }
        __syncthreads();   // buffer i (and A on i==0) visible to all

        const uint32_t bA = bbuf0 + (uint32_t)((i & 1) * SMEM_BBUF_BYTES) + bOff;
        const uint32_t aK = (uint32_t)(kseg * (KSEG * 2));

#pragma unroll
        for (int ks = 0; ks < 4; ks++) {
            uint32_t af[2][4];
            ldsm_x4(aAddr0 + aK + ks * 32, af[0][0], af[0][1], af[0][2], af[0][3]);
            ldsm_x4(aAddr1 + aK + ks * 32, af[1][0], af[1][1], af[1][2], af[1][3]);
            uint32_t bf[4][4];
#pragma unroll
            for (int nb = 0; nb < 4; nb++)
                ldsm_x4(bA + nb * (16 * BPAD * 2) + ks * 32,
                        bf[nb][0], bf[nb][1], bf[nb][2], bf[nb][3]);
#pragma unroll
            for (int mt = 0; mt < 2; mt++)
#pragma unroll
                for (int nb = 0; nb < 4; nb++) {
                    mma16816(acc[mt][nb * 2],     af[mt], bf[nb][0], bf[nb][1]);
                    mma16816(acc[mt][nb * 2 + 1], af[mt], bf[nb][2], bf[nb][3]);
                }
        }

        if (kseg == 7) {
            // ---- fused epilogue for this 256-n chunk ----
            const int nbase = chunk * NCHUNK + ngrp * 64;
#pragma unroll
            for (int mt = 0; mt < 2; mt++)
#pragma unroll
                for (int j = 0; j < 8; j++) {
                    int n = nbase + (j >> 1) * 16 + (j & 1) * 8 + qn;
                    float w0 = wq_s[n], w1 = wq_s[n + 1];
                    float v0 = v_s[n],  v1 = v_s[n + 1];
                    s[mt * 2]     = fmaf(v0, fast_tanh(w0 + acc[mt][j][0]), s[mt * 2]);
                    s[mt * 2]     = fmaf(v1, fast_tanh(w1 + acc[mt][j][1]), s[mt * 2]);
                    s[mt * 2 + 1] = fmaf(v0, fast_tanh(w0 + acc[mt][j][2]), s[mt * 2 + 1]);
                    s[mt * 2 + 1] = fmaf(v1, fast_tanh(w1 + acc[mt][j][3]), s[mt * 2 + 1]);
                }
        }
    }

    // ---- final reduction: quad shuffle + per-ngrp arrays ----
#pragma unroll
    for (int q = 0; q < 4; q++) {
        s[q] += __shfl_xor_sync(0xffffffffu, s[q], 1);
        s[q] += __shfl_xor_sync(0xffffffffu, s[q], 2);
    }
    if ((lane & 3) == 0) {
        const int rr = rbase + (lane >> 2);
        score4[ngrp][rr]      = s[0];
        score4[ngrp][rr + 8]  = s[1];
        score4[ngrp][rr + 16] = s[2];
        score4[ngrp][rr + 24] = s[3];
    }
    __syncthreads();
    if (tid < MTILE)
        out[r0 + tid] = (score4[0][tid] + score4[1][tid]) + (score4[2][tid] + score4[3][tid]);
}

// ======================= kernel 4: softmax over T, in-place =======================
__global__ void __launch_bounds__(256, 1) softmax_kernel(float* __restrict__ out) {
    __shared__ float red[256];
    float* p = out + (size_t)blockIdx.x * TLEN;
    int tid = threadIdx.x;
    float v[4];
    float m = -1e30f;
#pragma unroll
    for (int j = 0; j < 4; j++) { v[j] = p[tid + j * 256]; m = fmaxf(m, v[j]); }
    red[tid] = m; __syncthreads();
    for (int s = 128; s > 0; s >>= 1) {
        if (tid < s) red[tid] = fmaxf(red[tid], red[tid + s]);
        __syncthreads();
    }
    float mx = red[0];
    __syncthreads();
    float sum = 0.0f;
#pragma unroll
    for (int j = 0; j < 4; j++) { v[j] = __expf(v[j] - mx); sum += v[j]; }
    red[tid] = sum; __syncthreads();
    for (int s = 128; s > 0; s >>= 1) {
        if (tid < s) red[tid] += red[tid + s];
        __syncthreads();
    }
    float inv = 1.0f / red[0];
#pragma unroll
    for (int j = 0; j < 4; j++) p[tid + j * 256] = v[j] * inv;
}

// ======================= launch =======================
extern "C" void kernel_launch(void* const* d_in, const int* in_sizes, int n_in,
                              void* d_out, int out_size) {
    const float *dt = nullptr, *st = nullptr, *H = nullptr;
    const float *W = nullptr, *U = nullptr, *v = nullptr;
    int c32768 = 0, c262144 = 0;
    for (int i = 0; i < n_in; i++) {
        int s = in_sizes[i];
        if (s == 32768)          { if (c32768++ == 0) dt = (const float*)d_in[i]; else st = (const float*)d_in[i]; }
        else if (s == 67108864)  { H = (const float*)d_in[i]; }
        else if (s == 262144)    { if (c262144++ == 0) W = (const float*)d_in[i]; else U = (const float*)d_in[i]; }
        else if (s == 512)       { v = (const float*)d_in[i]; }
    }
    float* out = (float*)d_out;

    cudaFuncSetAttribute(attn_gemm_kernel, cudaFuncAttributeMaxDynamicSharedMemorySize, DYN_SMEM);

    pack_kernel<<<256, 256>>>(dt, st, U);
    wq_kernel<<<64, 128>>>(W);
    attn_gemm_kernel<<<1024, 512, DYN_SMEM>>>(H, v, out);
    softmax_kernel<<<128, 256>>>(out);
}

// round 5
// speedup vs baseline: 1.3556x; 1.0181x over previous
#include <cuda_runtime.h>
#include <cuda_fp16.h>
#include <cstdint>

// ======================= problem constants =======================
// B=128, T=1024, M=512 (GEMM N), P=256, K=512, rows = B*T = 131072
static constexpr int NB      = 128;
static constexpr int TLEN    = 1024;
static constexpr int MDIM    = 512;    // N of GEMM
static constexpr int KDIM    = 512;    // inner dim
static constexpr int MTILE   = 128;    // rows per CTA
static constexpr int NCHUNK  = 256;    // N per chunk (acc-resident)
static constexpr int NCHUNKS = MDIM / NCHUNK;    // 2
static constexpr int KSEG    = 64;     // K per B buffer / A conversion slice
static constexpr int KSEGS   = KDIM / KSEG;      // 8
static constexpr int NITER   = NCHUNKS * KSEGS;  // 16

// padded strides (halves): rotate bank groups -> conflict-free ldmatrix
static constexpr int APAD  = 520;      // 1040 B/row
static constexpr int BPAD  = 72;       // 144 B/row (64k + 8 pad)

static constexpr int SMEM_A_BYTES    = MTILE * APAD * 2;        // 133120
static constexpr int SMEM_BBUF_BYTES = NCHUNK * BPAD * 2;       // 36864
static constexpr int DYN_SMEM = SMEM_A_BYTES + 2 * SMEM_BBUF_BYTES;  // 206848

// ======================= scratch (device globals; no allocs) =======================
__device__ float g_Qt[KDIM * NB];                    // Q transposed [c][b]
__device__ float g_wq[NB * MDIM];                    // wq[b][n]
__device__ __align__(16) __half g_U16[MDIM * KDIM];  // U_d as fp16, [n][k]

// ======================= helpers =======================
__device__ __forceinline__ uint32_t smem_u32(const void* p) {
    return (uint32_t)__cvta_generic_to_shared(p);
}
__device__ __forceinline__ uint32_t pack_h2(float a, float b) {
    __half2 h = __floats2half2_rn(a, b);
    return *reinterpret_cast<uint32_t*>(&h);
}
__device__ __forceinline__ void ldsm_x4(uint32_t addr, uint32_t& r0, uint32_t& r1,
                                        uint32_t& r2, uint32_t& r3) {
    asm volatile("ldmatrix.sync.aligned.m8n8.x4.shared.b16 {%0,%1,%2,%3}, [%4];"
                 : "=r"(r0), "=r"(r1), "=r"(r2), "=r"(r3) : "r"(addr));
}
__device__ __forceinline__ void mma16816(float* c,
                                         const uint32_t* a,
                                         uint32_t b0, uint32_t b1) {
    asm volatile(
        "mma.sync.aligned.m16n8k16.row.col.f32.f16.f16.f32 "
        "{%0,%1,%2,%3}, {%4,%5,%6,%7}, {%8,%9}, {%0,%1,%2,%3};"
        : "+f"(c[0]), "+f"(c[1]), "+f"(c[2]), "+f"(c[3])
        : "r"(a[0]), "r"(a[1]), "r"(a[2]), "r"(a[3]), "r"(b0), "r"(b1));
}
__device__ __forceinline__ void cp_async16(uint32_t dst, const void* src) {
    asm volatile("cp.async.cg.shared.global [%0], [%1], 16;" :: "r"(dst), "l"(src));
}
__device__ __forceinline__ void cp_commit() {
    asm volatile("cp.async.commit_group;" ::: "memory");
}
__device__ __forceinline__ void cp_wait1() {
    asm volatile("cp.async.wait_group 1;" ::: "memory");
}
__device__ __forceinline__ void cp_wait0() {
    asm volatile("cp.async.wait_group 0;" ::: "memory");
}
// tanh(x) = 1 - 2/(e^{2x}+1): 2 MUFU + few ALU, rel err ~1e-6
__device__ __forceinline__ float fast_tanh(float x) {
    float e = __expf(x + x);
    return 1.0f - __fdividef(2.0f, e + 1.0f);
}

// ======================= kernel 1: pack Qt + U -> fp16 =======================
__global__ void __launch_bounds__(256, 1) pack_kernel(const float* __restrict__ dt,
                                                      const float* __restrict__ st,
                                                      const float* __restrict__ Ud) {
    int tid = blockIdx.x * blockDim.x + threadIdx.x;
    int stride = gridDim.x * blockDim.x;
    for (int i = tid; i < KDIM * NB; i += stride) {
        int c = i >> 7, b = i & (NB - 1);
        float v = (c < 256) ? dt[b * 256 + c] : st[b * 256 + (c - 256)];
        g_Qt[c * NB + b] = v;
    }
    for (int i = tid; i < MDIM * KDIM; i += stride)
        g_U16[i] = __float2half_rn(Ud[i]);
}

// ======================= kernel 2: wq[b][n] = sum_c q[b][c]*W_d[n][c] =======================
__global__ void __launch_bounds__(128, 1) wq_kernel(const float* __restrict__ Wd) {
    __shared__ float Ws[8 * KDIM];
    int nbase = blockIdx.x * 8;
    for (int i = threadIdx.x; i < 8 * KDIM; i += 128)
        Ws[i] = Wd[nbase * KDIM + i];
    __syncthreads();
    int b = threadIdx.x;
    float acc[8];
#pragma unroll
    for (int j = 0; j < 8; j++) acc[j] = 0.0f;
    for (int c = 0; c < KDIM; c++) {
        float qv = g_Qt[c * NB + b];
#pragma unroll
        for (int j = 0; j < 8; j++) acc[j] = fmaf(qv, Ws[j * KDIM + c], acc[j]);
    }
#pragma unroll
    for (int j = 0; j < 8; j++) g_wq[b * MDIM + nbase + j] = acc[j];
}

// ======================= dummy kernel: ncu slot steering =======================
__global__ void dummy_kernel() {}

// ======================= kernel 3: fused GEMM(HMMA) + tanh + v-dot =======================
// grid = 1024 CTAs, 512 threads (16 warps).
// warp w: rowgrp = w>>2 (32 rows each), ngrp = w&3 (64 n within a 256-n chunk)
__global__ void __launch_bounds__(512, 1) attn_gemm_kernel(const float* __restrict__ H,
                                                           const float* __restrict__ vd,
                                                           float* __restrict__ out) {
    extern __shared__ __align__(16) char dsm[];
    __half* smemA = reinterpret_cast<__half*>(dsm);
    char*   smemB = dsm + SMEM_A_BYTES;

    __shared__ float wq_s[MDIM];
    __shared__ float v_s[MDIM];
    __shared__ float score4[4][MTILE];

    const int tid  = threadIdx.x;
    const int wid  = tid >> 5;
    const int lane = tid & 31;
    const int blk  = blockIdx.x;
    const int batch = blk >> 3;
    const size_t r0 = (size_t)blk * MTILE;

    for (int i = tid; i < MDIM; i += 512) {
        wq_s[i] = g_wq[batch * MDIM + i];
        v_s[i]  = vd[i];
    }

    const uint32_t bbuf0 = smem_u32(smemB);

    // ---- issue B iter 0 (chunk 0, kseg 0) ----
    {
#pragma unroll
        for (int it = 0; it < 4; it++) {
            int idx = tid + it * 512;          // 2048 x 16B
            int row = idx >> 3, c16 = idx & 7;
            cp_async16(bbuf0 + (uint32_t)(row * (BPAD * 2) + c16 * 16),
                       (const char*)g_U16 + row * 1024 + c16 * 16);
        }
        cp_commit();
    }

    // ---- A conversion pipeline: per-kseg slices, 2-deep ----
    // thread handles row = tid>>2, 16 k at (kseg*64 + (tid&3)*16)
    const int arow = tid >> 2;
    const int aq   = (tid & 3) * 16;
    const float* aSrcRow = H + (r0 + (size_t)arow) * KDIM + aq;
    __half* aDstRow = smemA + arow * APAD + aq;

    float4 rA[4];
    // prologue: load slice 0, store it, load slice 1 into regs
    {
        const float4* s0 = reinterpret_cast<const float4*>(aSrcRow);
#pragma unroll
        for (int q = 0; q < 4; q++) rA[q] = s0[q];
        uint4 u0, u1;
        u0.x = pack_h2(rA[0].x, rA[0].y); u0.y = pack_h2(rA[0].z, rA[0].w);
        u0.z = pack_h2(rA[1].x, rA[1].y); u0.w = pack_h2(rA[1].z, rA[1].w);
        u1.x = pack_h2(rA[2].x, rA[2].y); u1.y = pack_h2(rA[2].z, rA[2].w);
        u1.z = pack_h2(rA[3].x, rA[3].y); u1.w = pack_h2(rA[3].z, rA[3].w);
        *reinterpret_cast<uint4*>(aDstRow)     = u0;
        *reinterpret_cast<uint4*>(aDstRow + 8) = u1;
        const float4* s1 = reinterpret_cast<const float4*>(aSrcRow + KSEG);
#pragma unroll
        for (int q = 0; q < 4; q++) rA[q] = s1[q];
    }

    // ---- per-lane ldmatrix addressing ----
    const int sub = lane >> 3;      // 8x8 tile index within x4
    const int l8  = lane & 7;
    const int rowgrp = wid >> 2;    // 4 rowgrps x 32 rows
    const int ngrp   = wid & 3;     // 4 ngrps x 64 n
    const int rbase  = rowgrp * 32;

    const uint32_t aAddr0 = smem_u32(smemA) +
        (uint32_t)(((rbase + (sub & 1) * 8 + l8) * APAD + (sub >> 1) * 8) * 2);
    const uint32_t aAddr1 = aAddr0 + (uint32_t)(16 * APAD * 2);
    const uint32_t bOff = (uint32_t)((ngrp * 64 + (sub >> 1) * 8 + l8) * (BPAD * 2) + (sub & 1) * 16);

    const int qn = (lane & 3) * 2;
    float s[4] = {0.0f, 0.0f, 0.0f, 0.0f};
    float acc[2][8][4];

    for (int i = 0; i < NITER; i++) {
        const int kseg  = i & 7;
        const int chunk = i >> 3;
        if (kseg == 0) {
#pragma unroll
            for (int mt = 0; mt < 2; mt++)
#pragma unroll
                for (int j = 0; j < 8; j++)
#pragma unroll
                    for (int q = 0; q < 4; q++) acc[mt][j][q] = 0.0f;
        }

        __syncthreads();   // all warps done reading buf[(i+1)&1] and A slice regions
        if (i + 1 < NITER) {
            const int j = i + 1;
            const int nb_g = (j >> 3) * NCHUNK;
            const int ks_g = (j & 7) * (KSEG * 2);
            const uint32_t dst = bbuf0 + (uint32_t)((j & 1) * SMEM_BBUF_BYTES);
#pragma unroll
            for (int it = 0; it < 4; it++) {
                int idx = tid + it * 512;
                int row = idx >> 3, c16 = idx & 7;
                cp_async16(dst + (uint32_t)(row * (BPAD * 2) + c16 * 16),
                           (const char*)g_U16 + (size_t)(nb_g + row) * 1024 + ks_g + c16 * 16);
            }
            cp_commit();
        }

        // ---- A pipeline: during chunk 0, store slice i+1, load slice i+2 ----
        if (i < 7) {
            uint4 u0, u1;
            u0.x = pack_h2(rA[0].x, rA[0].y); u0.y = pack_h2(rA[0].z, rA[0].w);
            u0.z = pack_h2(rA[1].x, rA[1].y); u0.w = pack_h2(rA[1].z, rA[1].w);
            u1.x = pack_h2(rA[2].x, rA[2].y); u1.y = pack_h2(rA[2].z, rA[2].w);
            u1.z = pack_h2(rA[3].x, rA[3].y); u1.w = pack_h2(rA[3].z, rA[3].w);
            __half* dstK = aDstRow + (i + 1) * KSEG;
            *reinterpret_cast<uint4*>(dstK)     = u0;
            *reinterpret_cast<uint4*>(dstK + 8) = u1;
            if (i + 2 < 8) {
                const float4* sN = reinterpret_cast<const float4*>(aSrcRow + (i + 2) * KSEG);
#pragma unroll
                for (int q = 0; q < 4; q++) rA[q] = sN[q];
            }
        }

        if (i + 1 < NITER) cp_wait1(); else cp_wait0();
        __syncthreads();   // buffer i + A slice i visible to all

        const uint32_t bA = bbuf0 + (uint32_t)((i & 1) * SMEM_BBUF_BYTES) + bOff;
        const uint32_t aK = (uint32_t)(kseg * (KSEG * 2));

#pragma unroll
        for (int ks = 0; ks < 4; ks++) {
            uint32_t af[2][4];
            ldsm_x4(aAddr0 + aK + ks * 32, af[0][0], af[0][1], af[0][2], af[0][3]);
            ldsm_x4(aAddr1 + aK + ks * 32, af[1][0], af[1][1], af[1][2], af[1][3]);
            uint32_t bf[4][4];
#pragma unroll
            for (int nb = 0; nb < 4; nb++)
                ldsm_x4(bA + nb * (16 * BPAD * 2) + ks * 32,
                        bf[nb][0], bf[nb][1], bf[nb][2], bf[nb][3]);
#pragma unroll
            for (int mt = 0; mt < 2; mt++)
#pragma unroll
                for (int nb = 0; nb < 4; nb++) {
                    mma16816(acc[mt][nb * 2],     af[mt], bf[nb][0], bf[nb][1]);
                    mma16816(acc[mt][nb * 2 + 1], af[mt], bf[nb][2], bf[nb][3]);
                }
        }

        if (kseg == 7) {
            const int nbase = chunk * NCHUNK + ngrp * 64;
#pragma unroll
            for (int mt = 0; mt < 2; mt++)
#pragma unroll
                for (int j = 0; j < 8; j++) {
                    int n = nbase + (j >> 1) * 16 + (j & 1) * 8 + qn;
                    float w0 = wq_s[n], w1 = wq_s[n + 1];
                    float v0 = v_s[n],  v1 = v_s[n + 1];
                    s[mt * 2]     = fmaf(v0, fast_tanh(w0 + acc[mt][j][0]), s[mt * 2]);
                    s[mt * 2]     = fmaf(v1, fast_tanh(w1 + acc[mt][j][1]), s[mt * 2]);
                    s[mt * 2 + 1] = fmaf(v0, fast_tanh(w0 + acc[mt][j][2]), s[mt * 2 + 1]);
                    s[mt * 2 + 1] = fmaf(v1, fast_tanh(w1 + acc[mt][j][3]), s[mt * 2 + 1]);
                }
        }
    }

    // ---- final reduction: quad shuffle + per-ngrp arrays ----
#pragma unroll
    for (int q = 0; q < 4; q++) {
        s[q] += __shfl_xor_sync(0xffffffffu, s[q], 1);
        s[q] += __shfl_xor_sync(0xffffffffu, s[q], 2);
    }
    if ((lane & 3) == 0) {
        const int rr = rbase + (lane >> 2);
        score4[ngrp][rr]      = s[0];
        score4[ngrp][rr + 8]  = s[1];
        score4[ngrp][rr + 16] = s[2];
        score4[ngrp][rr + 24] = s[3];
    }
    __syncthreads();
    if (tid < MTILE)
        out[r0 + tid] = (score4[0][tid] + score4[1][tid]) + (score4[2][tid] + score4[3][tid]);
}

// ======================= kernel 4: softmax over T, in-place =======================
__global__ void __launch_bounds__(256, 1) softmax_kernel(float* __restrict__ out) {
    __shared__ float red[256];
    float* p = out + (size_t)blockIdx.x * TLEN;
    int tid = threadIdx.x;
    float v[4];
    float m = -1e30f;
#pragma unroll
    for (int j = 0; j < 4; j++) { v[j] = p[tid + j * 256]; m = fmaxf(m, v[j]); }
    red[tid] = m; __syncthreads();
    for (int s = 128; s > 0; s >>= 1) {
        if (tid < s) red[tid] = fmaxf(red[tid], red[tid + s]);
        __syncthreads();
    }
    float mx = red[0];
    __syncthreads();
    float sum = 0.0f;
#pragma unroll
    for (int j = 0; j < 4; j++) { v[j] = __expf(v[j] - mx); sum += v[j]; }
    red[tid] = sum; __syncthreads();
    for (int s = 128; s > 0; s >>= 1) {
        if (tid < s) red[tid] += red[tid + s];
        __syncthreads();
    }
    float inv = 1.0f / red[0];
#pragma unroll
    for (int j = 0; j < 4; j++) p[tid + j * 256] = v[j] * inv;
}

// ======================= launch =======================
extern "C" void kernel_launch(void* const* d_in, const int* in_sizes, int n_in,
                              void* d_out, int out_size) {
    const float *dt = nullptr, *st = nullptr, *H = nullptr;
    const float *W = nullptr, *U = nullptr, *v = nullptr;
    int c32768 = 0, c262144 = 0;
    for (int i = 0; i < n_in; i++) {
        int s = in_sizes[i];
        if (s == 32768)          { if (c32768++ == 0) dt = (const float*)d_in[i]; else st = (const float*)d_in[i]; }
        else if (s == 67108864)  { H = (const float*)d_in[i]; }
        else if (s == 262144)    { if (c262144++ == 0) W = (const float*)d_in[i]; else U = (const float*)d_in[i]; }
        else if (s == 512)       { v = (const float*)d_in[i]; }
    }
    float* out = (float*)d_out;

    cudaFuncSetAttribute(attn_gemm_kernel, cudaFuncAttributeMaxDynamicSharedMemorySize, DYN_SMEM);

    pack_kernel<<<256, 256>>>(dt, st, U);
    wq_kernel<<<64, 128>>>(W);
    dummy_kernel<<<1, 32>>>();   // steer ncu -s 5 slot onto attn_gemm_kernel
    attn_gemm_kernel<<<1024, 512, DYN_SMEM>>>(H, v, out);
    softmax_kernel<<<128, 256>>>(out);
}